// round 11
// baseline (speedup 1.0000x reference)
#include <cuda_runtime.h>

#define XS    128
#define BATCH 8
#define MPTS  500000
#define NQUART  (BATCH * XS * 4)             // 4096 quarter-planes
#define GRID_ELEMS (BATCH * XS * XS * XS)    // 64 MiB
#define TPB_SCAT (MPTS / 8)                  // 62,500 scatter threads / batch
#define SCAT_BLK_B 245                       // ceil(62500/256)
#define RED_BLK_B 256                        // 64 plane-pairs x 4 quarters

// Device scratch (zero-init at load; all counters self-reset per call)
__device__ float g_grid[GRID_ELEMS];
__device__ int   g_done[NQUART];
__device__ unsigned g_scnt[BATCH];
__device__ unsigned g_rcnt[BATCH];
__device__ float g_acc_tv[BATCH];
__device__ float g_acc_mse[BATCH];

// ---- scoped signaling ----
__device__ __forceinline__ void red_release_add(unsigned* p, unsigned v) {
    asm volatile("red.release.gpu.add.u32 [%0], %1;" :: "l"(p), "r"(v) : "memory");
}
__device__ __forceinline__ unsigned atom_acqrel_add(unsigned* p, unsigned v) {
    unsigned r;
    asm volatile("atom.acq_rel.gpu.add.u32 %0, [%1], %2;"
                 : "=r"(r) : "l"(p), "r"(v) : "memory");
    return r;
}
__device__ __forceinline__ unsigned ld_acquire(const unsigned* p) {
    unsigned r;
    asm volatile("ld.acquire.gpu.u32 %0, [%1];" : "=r"(r) : "l"(p) : "memory");
    return r;
}
__device__ __forceinline__ float ldf_acquire(const float* p) {
    float r;
    asm volatile("ld.acquire.gpu.f32 %0, [%1];" : "=f"(r) : "l"(p) : "memory");
    return r;
}

// ---------------------------------------------------------------------------
// Per-batch scatter: 245 blocks, 8 points/thread. Fires the PDL trigger at
// entry so the next kernel in the chain can co-schedule immediately.
// ---------------------------------------------------------------------------
__global__ void __launch_bounds__(256) scatter_kernel(
        const int4*   __restrict__ idx4,
        const float4* __restrict__ val4,
        int b) {
    asm volatile("griddepcontrol.launch_dependents;");

    int t = blockIdx.x * 256 + threadIdx.x;
    if (t < TPB_SCAT) {
        long base = (long)b << 21;
        long p0   = (long)b * MPTS + (long)t * 8;
        int4 a[6];
        #pragma unroll
        for (int s = 0; s < 6; s++) a[s] = __ldcs(&idx4[(p0 * 3) / 4 + s]);
        float4 v0 = __ldcs(&val4[p0 / 4 + 0]);
        float4 v1 = __ldcs(&val4[p0 / 4 + 1]);
        const int* ai = (const int*)a;
        float vals[8] = { v0.x, v0.y, v0.z, v0.w, v1.x, v1.y, v1.z, v1.w };
        #pragma unroll
        for (int s = 0; s < 8; s++) {
            long off = base + ((long)ai[3 * s] << 14) + (ai[3 * s + 1] << 7)
                            + ai[3 * s + 2];
            atomicAdd(&g_grid[off], vals[s]);
        }
    }
    __syncthreads();                            // all REDs program-ordered
    if (threadIdx.x == 0) red_release_add(&g_scnt[b], 1u);
}

// ---- reduce helpers ----
__device__ __forceinline__ void diff4(const float4& a, const float4& b,
                                      float& tv, float& mse) {
    float d0 = b.x - a.x, d1 = b.y - a.y, d2 = b.z - a.z, d3 = b.w - a.w;
    tv  += fabsf(d0) + fabsf(d1) + fabsf(d2) + fabsf(d3);
    mse += d0 * d0 + d1 * d1 + d2 * d2 + d3 * d3;
}
__device__ __forceinline__ void kdiffs(const float4& c, bool cross,
                                       float& tv, float& mse) {
    float d0 = c.y - c.x, d1 = c.z - c.y, d2 = c.w - c.z;
    tv  += fabsf(d0) + fabsf(d1) + fabsf(d2);
    mse += d0 * d0 + d1 * d1 + d2 * d2;
    float nx = __shfl_down_sync(0xffffffffu, c.x, 1);
    if (cross) { float d3 = nx - c.w; tv += fabsf(d3); mse += d3 * d3; }
}
__device__ __forceinline__ void plane_kj(const float4 c[4], const float4& jb,
                                         bool has_jb, bool crossk,
                                         float& tv, float& mse) {
    #pragma unroll
    for (int r = 0; r < 4; r++) kdiffs(c[r], crossk, tv, mse);
    diff4(c[0], c[1], tv, mse);
    diff4(c[1], c[2], tv, mse);
    diff4(c[2], c[3], tv, mse);
    if (has_jb) diff4(c[3], jb, tv, mse);
}
__device__ __forceinline__ void zero_quarter(int qidx, int tid) {
    float4* gw = (float4*)g_grid;
    const long qb = (long)qidx << 10;
    const float4 z = make_float4(0.f, 0.f, 0.f, 0.f);
    #pragma unroll
    for (int it = 0; it < 4; ++it)
        gw[qb + it * 256 + tid] = z;
    if (tid == 0) g_done[qidx] = 0;
}

// ---------------------------------------------------------------------------
// Per-batch reduce + re-zero: 256 blocks (plane-pair x quarter), R7 tiling.
// Launched one batch behind its scatter in the chain, so the counter wait
// passes ~immediately; it co-runs with the NEXT batch's scatter.
// ---------------------------------------------------------------------------
__global__ void __launch_bounds__(256, 6) reduce_zero_kernel(
        float* __restrict__ d_out, int b) {
    asm volatile("griddepcontrol.launch_dependents;");

    const int lg    = blockIdx.x >> 2;             // plane-pair in batch 0..63
    const int q     = blockIdx.x & 3;
    const int p0    = b * XS + lg * 2;             // even global plane
    const int i0    = lg * 2;
    const int lane  = threadIdx.x & 31;
    const int wg    = threadIdx.x >> 5;
    const int jrow0 = q * 32 + wg * 4;
    const bool has_jb = (jrow0 + 4) < XS;
    const bool crossk = (lane != 31);
    const float4* __restrict__ g4 = (const float4*)g_grid;

    if (threadIdx.x == 0) {
        while (ld_acquire(&g_scnt[b]) < SCAT_BLK_B) __nanosleep(64);
    }
    __syncthreads();

    const long pb0 = (long)p0 << 12;
    const int  fo  = jrow0 * 32 + lane;
    const float4 z = make_float4(0.f, 0.f, 0.f, 0.f);

    float tv = 0.f, mse = 0.f;
    float4 c[4], n[4];

    #pragma unroll
    for (int r = 0; r < 4; r++) c[r] = g4[pb0 + fo + r * 32];
    float4 jb0 = has_jb ? g4[pb0 + fo + 128] : z;
    plane_kj(c, jb0, has_jb, crossk, tv, mse);

    const long pb1 = pb0 + 4096;
    #pragma unroll
    for (int r = 0; r < 4; r++) n[r] = g4[pb1 + fo + r * 32];
    #pragma unroll
    for (int r = 0; r < 4; r++) diff4(c[r], n[r], tv, mse);
    float4 jb1 = has_jb ? g4[pb1 + fo + 128] : z;
    plane_kj(n, jb1, has_jb, crossk, tv, mse);

    const bool has_ext = (i0 < XS - 2);
    if (has_ext) {
        const long pb2 = pb1 + 4096;
        #pragma unroll
        for (int r = 0; r < 4; r++) {
            float4 e = g4[pb2 + fo + r * 32];
            diff4(n[r], e, tv, mse);
        }
    }

    #pragma unroll
    for (int off = 16; off > 0; off >>= 1) {
        tv  += __shfl_down_sync(0xffffffffu, tv,  off);
        mse += __shfl_down_sync(0xffffffffu, mse, off);
    }
    __shared__ float stv[8], smse[8];
    if (lane == 0) { stv[wg] = tv; smse[wg] = mse; }
    __syncthreads();
    float bptv = 0.f, bpmse = 0.f;
    if (threadIdx.x == 0) {
        #pragma unroll
        for (int s = 0; s < 8; s++) { bptv += stv[s]; bpmse += smse[s]; }
    }

    // ---- quarter-granular zero protocol (per batch; R7 form) ----
    __shared__ int zmask;
    if (threadIdx.x == 0) zmask = 0;
    __syncthreads();
    if (threadIdx.x == 0) {
        __threadfence();
        int m = 0;
        int q0 = (p0 << 2) + q;
        int q1 = ((p0 + 1) << 2) + q;
        int tgt0 = 1 + (q > 0 ? 1 : 0) + (i0 > 0 ? 1 : 0);
        int tgt1 = 1 + (q > 0 ? 1 : 0);
        if (atomicAdd(&g_done[q0], 1) + 1 == tgt0) m |= 1;
        if (atomicAdd(&g_done[q1], 1) + 1 == tgt1) m |= 2;
        if (q < 3) {
            int j0 = (p0 << 2) + q + 1;
            int j1 = ((p0 + 1) << 2) + q + 1;
            if (atomicAdd(&g_done[j0], 1) + 1 == 2 + (i0 > 0 ? 1 : 0)) m |= 4;
            if (atomicAdd(&g_done[j1], 1) + 1 == 2) m |= 8;
        }
        if (has_ext) {
            int e0 = ((p0 + 2) << 2) + q;
            if (atomicAdd(&g_done[e0], 1) + 1 == 2 + (q > 0 ? 1 : 0)) m |= 16;
        }
        zmask = m;
    }
    __syncthreads();
    int m = zmask;
    if (m & 1)  zero_quarter((p0 << 2) + q,           threadIdx.x);
    if (m & 2)  zero_quarter(((p0 + 1) << 2) + q,     threadIdx.x);
    if (m & 4)  zero_quarter((p0 << 2) + q + 1,       threadIdx.x);
    if (m & 8)  zero_quarter(((p0 + 1) << 2) + q + 1, threadIdx.x);
    if (m & 16) zero_quarter(((p0 + 2) << 2) + q,     threadIdx.x);

    // ---- publish partials; last reducer of batch finalizes d_out ----
    if (threadIdx.x == 0) {
        atomicAdd(&g_acc_tv[b],  bptv);
        atomicAdd(&g_acc_mse[b], bpmse);
        unsigned prev = atom_acqrel_add(&g_rcnt[b], 1u);
        if (prev == RED_BLK_B - 1) {
            float ttv  = ldf_acquire(&g_acc_tv[b]);
            float tmse = ldf_acquire(&g_acc_mse[b]);
            const float tv_norm  = 1.f / (float)(XS * XS * XS);
            const float mse_norm = 1.f / (float)(2 * XS * XS - 2 * XS);
            d_out[b]         = ttv  * tv_norm;
            d_out[BATCH + b] = tmse * mse_norm;
            g_acc_tv[b]  = 0.f;
            g_acc_mse[b] = 0.f;
            g_rcnt[b] = 0u;
            g_scnt[b] = 0u;
        }
    }
}

// ---------------------------------------------------------------------------
static inline void launch_pdl(void* func, dim3 grid, void** args) {
    cudaLaunchAttribute attrs[1];
    attrs[0].id = cudaLaunchAttributeProgrammaticStreamSerialization;
    attrs[0].val.programmaticStreamSerializationAllowed = 1;
    cudaLaunchConfig_t cfg = {};
    cfg.gridDim  = grid;
    cfg.blockDim = dim3(256);
    cfg.dynamicSmemBytes = 0;
    cfg.stream = 0;
    cfg.attrs = attrs;
    cfg.numAttrs = 1;
    cudaLaunchKernelExC(&cfg, func, args);
}

extern "C" void kernel_launch(void* const* d_in, const int* in_sizes, int n_in,
                              void* d_out, int out_size) {
    const int4*   idx4 = (const int4*)d_in[0];     // (B, M, 3) int32
    const float4* val4 = (const float4*)d_in[1];   // (B, M) float32
    float* out = (float*)d_out;                    // (2, B) float32

    static int sb[BATCH] = {0,1,2,3,4,5,6,7};

    // Chain: S0, S1, R0, S2, R1, ..., S7, R6, R7 — every kernel fires the PDL
    // trigger at entry, so the whole chain co-schedules in launch order and
    // R(b) always finds S(b) complete (counter wait ~free) while overlapping
    // S(b+1). Correctness is carried by the release/acquire counters, not PDL.
    {
        void* a0[] = { (void*)&idx4, (void*)&val4, (void*)&sb[0] };
        launch_pdl((void*)scatter_kernel, dim3(SCAT_BLK_B), a0);
    }
    for (int b = 1; b < BATCH; ++b) {
        void* as[] = { (void*)&idx4, (void*)&val4, (void*)&sb[b] };
        launch_pdl((void*)scatter_kernel, dim3(SCAT_BLK_B), as);
        void* ar[] = { (void*)&out, (void*)&sb[b - 1] };
        launch_pdl((void*)reduce_zero_kernel, dim3(RED_BLK_B), ar);
    }
    {
        void* ar[] = { (void*)&out, (void*)&sb[BATCH - 1] };
        launch_pdl((void*)reduce_zero_kernel, dim3(RED_BLK_B), ar);
    }
}

// round 12
// speedup vs baseline: 1.1338x; 1.1338x over previous
#include <cuda_runtime.h>

#define XS    128
#define BATCH 8
#define MPTS  500000
#define NQUART  (BATCH * XS * 4)             // 4096 quarter-planes
#define GRID_ELEMS (BATCH * XS * XS * XS)    // 64 MiB
#define TPB_SCAT (MPTS / 8)                  // 62,500 scatter threads / batch

// Scratch (device globals: zero-initialized at load; g_done self-resets)
__device__ float g_grid[GRID_ELEMS];
__device__ int   g_done[NQUART];

// ---------------------------------------------------------------------------
// Kernel 1: scatter-add (R7 form, proven 32 us). 8 points/thread, streaming
// loads, 8 REDs/thread. Block 0 zeroes the 16 output accumulators.
// ---------------------------------------------------------------------------
__global__ void __launch_bounds__(256) scatter_kernel(
        const int4*   __restrict__ idx4,
        const float4* __restrict__ val4,
        float*        __restrict__ d_out) {
    if (blockIdx.x == 0 && threadIdx.x < 2 * BATCH) d_out[threadIdx.x] = 0.f;

    const int nthreads = BATCH * TPB_SCAT;          // 500,000
    int tid = blockIdx.x * blockDim.x + threadIdx.x;
    if (tid >= nthreads) return;

    int b = tid / TPB_SCAT;
    int t = tid - b * TPB_SCAT;
    long base = (long)b << 21;
    long p0   = (long)b * MPTS + (long)t * 8;

    int4 a[6];
    #pragma unroll
    for (int s = 0; s < 6; s++) a[s] = __ldcs(&idx4[(p0 * 3) / 4 + s]);
    float4 v0 = __ldcs(&val4[p0 / 4 + 0]);
    float4 v1 = __ldcs(&val4[p0 / 4 + 1]);
    const int* ai = (const int*)a;
    float vals[8] = { v0.x, v0.y, v0.z, v0.w, v1.x, v1.y, v1.z, v1.w };

    #pragma unroll
    for (int s = 0; s < 8; s++) {
        long off = base + ((long)ai[3 * s] << 14) + (ai[3 * s + 1] << 7)
                        + ai[3 * s + 2];
        atomicAdd(&g_grid[off], vals[s]);
    }
}

// ---------------------------------------------------------------------------
__device__ __forceinline__ void diff4(const float4& a, const float4& b,
                                      float& tv, float& mse) {
    float d0 = b.x - a.x, d1 = b.y - a.y, d2 = b.z - a.z, d3 = b.w - a.w;
    tv  += fabsf(d0) + fabsf(d1) + fabsf(d2) + fabsf(d3);
    mse += d0 * d0 + d1 * d1 + d2 * d2 + d3 * d3;
}
__device__ __forceinline__ void kdiffs(const float4& c, bool cross,
                                       float& tv, float& mse) {
    float d0 = c.y - c.x, d1 = c.z - c.y, d2 = c.w - c.z;
    tv  += fabsf(d0) + fabsf(d1) + fabsf(d2);
    mse += d0 * d0 + d1 * d1 + d2 * d2;
    float nx = __shfl_down_sync(0xffffffffu, c.x, 1);
    if (cross) { float d3 = nx - c.w; tv += fabsf(d3); mse += d3 * d3; }
}
__device__ __forceinline__ void plane_kj(const float4 c[4], const float4& jb,
                                         bool has_jb, bool crossk,
                                         float& tv, float& mse) {
    #pragma unroll
    for (int r = 0; r < 4; r++) kdiffs(c[r], crossk, tv, mse);
    diff4(c[0], c[1], tv, mse);
    diff4(c[1], c[2], tv, mse);
    diff4(c[2], c[3], tv, mse);
    if (has_jb) diff4(c[3], jb, tv, mse);
}
__device__ __forceinline__ void zero_quarter(int qidx, int tid) {
    float4* gw = (float4*)g_grid;
    const long qb = (long)qidx << 10;
    const float4 z = make_float4(0.f, 0.f, 0.f, 0.f);
    #pragma unroll
    for (int it = 0; it < 4; ++it)
        gw[qb + it * 256 + tid] = z;
    if (tid == 0) g_done[qidx] = 0;
}

// ---------------------------------------------------------------------------
// Kernel 2: TV+MSE reduce + re-zero, plane-pair blocks (2048), MLP-first:
// ALL 10 loads of planes p0/p1 issue before any compute (ptxas front-batch),
// ext-plane loads reuse the dead c[] registers and issue before p1 compute.
// __launch_bounds__(256, 4) -> 64-reg budget so the batch fits in registers.
// ---------------------------------------------------------------------------
__global__ void __launch_bounds__(256, 4) reduce_zero_kernel(float* __restrict__ d_out) {
    const int group = blockIdx.x >> 2;             // 0..511
    const int q     = blockIdx.x & 3;
    const int p0    = group * 2;                   // even global plane
    const int b     = p0 >> 7;
    const int i0    = p0 & 127;
    const int lane  = threadIdx.x & 31;
    const int wg    = threadIdx.x >> 5;
    const int jrow0 = q * 32 + wg * 4;
    const bool has_jb = (jrow0 + 4) < XS;
    const bool crossk = (lane != 31);
    const float4* __restrict__ g4 = (const float4*)g_grid;

    const long pb0 = (long)p0 << 12;
    const long pb1 = pb0 + 4096;
    const int  fo  = jrow0 * 32 + lane;
    const float4 z = make_float4(0.f, 0.f, 0.f, 0.f);

    float tv = 0.f, mse = 0.f;
    float4 c[4], n[4], jb0, jb1;

    // ---- load phase: 10 independent LDG.128 (front-batched) ----
    #pragma unroll
    for (int r = 0; r < 4; r++) c[r] = g4[pb0 + fo + r * 32];
    jb0 = has_jb ? g4[pb0 + fo + 128] : z;
    #pragma unroll
    for (int r = 0; r < 4; r++) n[r] = g4[pb1 + fo + r * 32];
    jb1 = has_jb ? g4[pb1 + fo + 128] : z;

    // ---- compute p0 + i-diffs; then recycle c[] for the ext plane ----
    plane_kj(c, jb0, has_jb, crossk, tv, mse);
    #pragma unroll
    for (int r = 0; r < 4; r++) diff4(c[r], n[r], tv, mse);

    const bool has_ext = (i0 < XS - 2);
    if (has_ext) {                                  // ext loads issue BEFORE
        const long pb2 = pb1 + 4096;                // p1 compute (c[] dead)
        #pragma unroll
        for (int r = 0; r < 4; r++) c[r] = g4[pb2 + fo + r * 32];
    }
    plane_kj(n, jb1, has_jb, crossk, tv, mse);
    if (has_ext) {
        #pragma unroll
        for (int r = 0; r < 4; r++) diff4(n[r], c[r], tv, mse);
    }

    // ---- block reduce -> 2 atomics into d_out ----
    #pragma unroll
    for (int off = 16; off > 0; off >>= 1) {
        tv  += __shfl_down_sync(0xffffffffu, tv,  off);
        mse += __shfl_down_sync(0xffffffffu, mse, off);
    }
    __shared__ float stv[8], smse[8];
    if (lane == 0) { stv[wg] = tv; smse[wg] = mse; }
    __syncthreads();
    if (threadIdx.x == 0) {
        float ttv = 0.f, tmse = 0.f;
        #pragma unroll
        for (int s = 0; s < 8; s++) { ttv += stv[s]; tmse += smse[s]; }
        const float tv_norm  = 1.f / (float)(XS * XS * XS);
        const float mse_norm = 1.f / (float)(2 * XS * XS - 2 * XS);
        atomicAdd(&d_out[b],         ttv  * tv_norm);
        atomicAdd(&d_out[BATCH + b], tmse * mse_norm);
    }

    // ---- quarter-granular zero protocol (R7 form, proven) ----
    __shared__ int zmask;
    if (threadIdx.x == 0) zmask = 0;
    __syncthreads();                                // all grid reads retired
    if (threadIdx.x == 0) {
        __threadfence();
        int m = 0;
        int q0 = (p0 << 2) + q;
        int q1 = ((p0 + 1) << 2) + q;
        int tgt0 = 1 + (q > 0 ? 1 : 0) + (i0 > 0 ? 1 : 0);
        int tgt1 = 1 + (q > 0 ? 1 : 0);
        if (atomicAdd(&g_done[q0], 1) + 1 == tgt0) m |= 1;
        if (atomicAdd(&g_done[q1], 1) + 1 == tgt1) m |= 2;
        if (q < 3) {
            int j0 = (p0 << 2) + q + 1;
            int j1 = ((p0 + 1) << 2) + q + 1;
            if (atomicAdd(&g_done[j0], 1) + 1 == 2 + (i0 > 0 ? 1 : 0)) m |= 4;
            if (atomicAdd(&g_done[j1], 1) + 1 == 2) m |= 8;
        }
        if (has_ext) {
            int e0 = ((p0 + 2) << 2) + q;
            if (atomicAdd(&g_done[e0], 1) + 1 == 2 + (q > 0 ? 1 : 0)) m |= 16;
        }
        zmask = m;
    }
    __syncthreads();
    int m = zmask;
    if (m & 1)  zero_quarter((p0 << 2) + q,           threadIdx.x);
    if (m & 2)  zero_quarter(((p0 + 1) << 2) + q,     threadIdx.x);
    if (m & 4)  zero_quarter((p0 << 2) + q + 1,       threadIdx.x);
    if (m & 8)  zero_quarter(((p0 + 1) << 2) + q + 1, threadIdx.x);
    if (m & 16) zero_quarter(((p0 + 2) << 2) + q,     threadIdx.x);
}

// ---------------------------------------------------------------------------
extern "C" void kernel_launch(void* const* d_in, const int* in_sizes, int n_in,
                              void* d_out, int out_size) {
    const int*   indices = (const int*)d_in[0];    // (B, M, 3) int32
    const float* values  = (const float*)d_in[1];  // (B, M) float32
    float* out = (float*)d_out;                    // (2, B) float32

    {
        int nthreads = BATCH * TPB_SCAT;            // 500,000
        int threads = 256;
        int blocks = (nthreads + threads - 1) / threads;
        scatter_kernel<<<blocks, threads>>>((const int4*)indices,
                                            (const float4*)values, out);
    }
    {
        reduce_zero_kernel<<<2048, 256>>>(out);
    }
}

// round 13
// speedup vs baseline: 1.2481x; 1.1009x over previous
#include <cuda_runtime.h>
#include <cstdint>

#define XS    128
#define BATCH 8
#define MPTS  500000
#define NQUART  (BATCH * XS * 4)             // 4096 quarter-planes
#define GRID_ELEMS (BATCH * XS * XS * XS)    // 64 MiB
#define TPB_SCAT (MPTS / 8)                  // 62,500 scatter threads / batch

// Scratch (device globals: zero-initialized at load; g_done self-resets)
__device__ float g_grid[GRID_ELEMS];
__device__ int   g_done[NQUART];

// ---- L2 evict-last cache-policy helpers (device-side, capture-safe) ----
__device__ __forceinline__ uint64_t mk_evict_last() {
    uint64_t pol;
    asm("createpolicy.fractional.L2::evict_last.b64 %0, 1.0;" : "=l"(pol));
    return pol;
}
__device__ __forceinline__ void red_add_el(float* p, float v, uint64_t pol) {
    asm volatile("red.global.L2::cache_hint.add.f32 [%0], %1, %2;"
                 :: "l"(p), "f"(v), "l"(pol) : "memory");
}
__device__ __forceinline__ float4 ldg4_el(const float4* p, uint64_t pol) {
    float4 r;
    asm volatile("ld.global.L2::cache_hint.v4.f32 {%0,%1,%2,%3}, [%4], %5;"
                 : "=f"(r.x), "=f"(r.y), "=f"(r.z), "=f"(r.w)
                 : "l"(p), "l"(pol) : "memory");
    return r;
}
__device__ __forceinline__ void stg4_el(float4* p, float4 v, uint64_t pol) {
    asm volatile("st.global.L2::cache_hint.v4.f32 [%0], {%1,%2,%3,%4}, %5;"
                 :: "l"(p), "f"(v.x), "f"(v.y), "f"(v.z), "f"(v.w), "l"(pol)
                 : "memory");
}

// ---------------------------------------------------------------------------
// Kernel 1: scatter-add. 8 points/thread, streaming (__ldcs) input loads,
// 8 evict-last REDs/thread with 32-bit element offsets. Block 0 zeroes d_out.
// ---------------------------------------------------------------------------
__global__ void __launch_bounds__(256) scatter_kernel(
        const int4*   __restrict__ idx4,
        const float4* __restrict__ val4,
        float*        __restrict__ d_out) {
    if (blockIdx.x == 0 && threadIdx.x < 2 * BATCH) d_out[threadIdx.x] = 0.f;

    const int nthreads = BATCH * TPB_SCAT;          // 500,000
    int tid = blockIdx.x * blockDim.x + threadIdx.x;
    if (tid >= nthreads) return;

    const uint64_t pol = mk_evict_last();

    int b = tid / TPB_SCAT;
    int t = tid - b * TPB_SCAT;
    unsigned base = (unsigned)b << 21;              // element offset, fits u32
    long p0 = (long)b * MPTS + (long)t * 8;

    int4 a[6];
    #pragma unroll
    for (int s = 0; s < 6; s++) a[s] = __ldcs(&idx4[(p0 * 3) / 4 + s]);
    float4 v0 = __ldcs(&val4[p0 / 4 + 0]);
    float4 v1 = __ldcs(&val4[p0 / 4 + 1]);
    const int* ai = (const int*)a;
    float vals[8] = { v0.x, v0.y, v0.z, v0.w, v1.x, v1.y, v1.z, v1.w };

    #pragma unroll
    for (int s = 0; s < 8; s++) {
        unsigned off = base + ((unsigned)ai[3 * s] << 14)
                     + ((unsigned)ai[3 * s + 1] << 7) + (unsigned)ai[3 * s + 2];
        red_add_el(&g_grid[off], vals[s], pol);
    }
}

// ---------------------------------------------------------------------------
__device__ __forceinline__ void diff4(const float4& a, const float4& b,
                                      float& tv, float& mse) {
    float d0 = b.x - a.x, d1 = b.y - a.y, d2 = b.z - a.z, d3 = b.w - a.w;
    tv  += fabsf(d0) + fabsf(d1) + fabsf(d2) + fabsf(d3);
    mse += d0 * d0 + d1 * d1 + d2 * d2 + d3 * d3;
}
__device__ __forceinline__ void kdiffs(const float4& c, bool cross,
                                       float& tv, float& mse) {
    float d0 = c.y - c.x, d1 = c.z - c.y, d2 = c.w - c.z;
    tv  += fabsf(d0) + fabsf(d1) + fabsf(d2);
    mse += d0 * d0 + d1 * d1 + d2 * d2;
    float nx = __shfl_down_sync(0xffffffffu, c.x, 1);
    if (cross) { float d3 = nx - c.w; tv += fabsf(d3); mse += d3 * d3; }
}
__device__ __forceinline__ void plane_kj(const float4 c[4], const float4& jb,
                                         bool has_jb, bool crossk,
                                         float& tv, float& mse) {
    #pragma unroll
    for (int r = 0; r < 4; r++) kdiffs(c[r], crossk, tv, mse);
    diff4(c[0], c[1], tv, mse);
    diff4(c[1], c[2], tv, mse);
    diff4(c[2], c[3], tv, mse);
    if (has_jb) diff4(c[3], jb, tv, mse);
}
__device__ __forceinline__ void zero_quarter(int qidx, int tid, uint64_t pol) {
    float4* gw = (float4*)g_grid;
    const long qb = (long)qidx << 10;
    const float4 z = make_float4(0.f, 0.f, 0.f, 0.f);
    #pragma unroll
    for (int it = 0; it < 4; ++it)
        stg4_el(&gw[qb + it * 256 + tid], z, pol);
    if (tid == 0) g_done[qidx] = 0;
}

// ---------------------------------------------------------------------------
// Kernel 2: TV+MSE reduce + re-zero, plane-pair blocks (2048), MLP-first
// load schedule (R12), all grid accesses evict-last.
// ---------------------------------------------------------------------------
__global__ void __launch_bounds__(256, 4) reduce_zero_kernel(float* __restrict__ d_out) {
    const int group = blockIdx.x >> 2;             // 0..511
    const int q     = blockIdx.x & 3;
    const int p0    = group * 2;                   // even global plane
    const int b     = p0 >> 7;
    const int i0    = p0 & 127;
    const int lane  = threadIdx.x & 31;
    const int wg    = threadIdx.x >> 5;
    const int jrow0 = q * 32 + wg * 4;
    const bool has_jb = (jrow0 + 4) < XS;
    const bool crossk = (lane != 31);
    const float4* __restrict__ g4 = (const float4*)g_grid;

    const uint64_t pol = mk_evict_last();

    const long pb0 = (long)p0 << 12;
    const long pb1 = pb0 + 4096;
    const int  fo  = jrow0 * 32 + lane;
    const float4 z = make_float4(0.f, 0.f, 0.f, 0.f);

    float tv = 0.f, mse = 0.f;
    float4 c[4], n[4], jb0, jb1;

    // ---- load phase: 10 independent LDG.128 (front-batched, evict-last) ----
    #pragma unroll
    for (int r = 0; r < 4; r++) c[r] = ldg4_el(&g4[pb0 + fo + r * 32], pol);
    jb0 = has_jb ? ldg4_el(&g4[pb0 + fo + 128], pol) : z;
    #pragma unroll
    for (int r = 0; r < 4; r++) n[r] = ldg4_el(&g4[pb1 + fo + r * 32], pol);
    jb1 = has_jb ? ldg4_el(&g4[pb1 + fo + 128], pol) : z;

    // ---- compute p0 + i-diffs; recycle c[] for the ext plane ----
    plane_kj(c, jb0, has_jb, crossk, tv, mse);
    #pragma unroll
    for (int r = 0; r < 4; r++) diff4(c[r], n[r], tv, mse);

    const bool has_ext = (i0 < XS - 2);
    if (has_ext) {
        const long pb2 = pb1 + 4096;
        #pragma unroll
        for (int r = 0; r < 4; r++) c[r] = ldg4_el(&g4[pb2 + fo + r * 32], pol);
    }
    plane_kj(n, jb1, has_jb, crossk, tv, mse);
    if (has_ext) {
        #pragma unroll
        for (int r = 0; r < 4; r++) diff4(n[r], c[r], tv, mse);
    }

    // ---- block reduce -> 2 atomics into d_out ----
    #pragma unroll
    for (int off = 16; off > 0; off >>= 1) {
        tv  += __shfl_down_sync(0xffffffffu, tv,  off);
        mse += __shfl_down_sync(0xffffffffu, mse, off);
    }
    __shared__ float stv[8], smse[8];
    if (lane == 0) { stv[wg] = tv; smse[wg] = mse; }
    __syncthreads();
    if (threadIdx.x == 0) {
        float ttv = 0.f, tmse = 0.f;
        #pragma unroll
        for (int s = 0; s < 8; s++) { ttv += stv[s]; tmse += smse[s]; }
        const float tv_norm  = 1.f / (float)(XS * XS * XS);
        const float mse_norm = 1.f / (float)(2 * XS * XS - 2 * XS);
        atomicAdd(&d_out[b],         ttv  * tv_norm);
        atomicAdd(&d_out[BATCH + b], tmse * mse_norm);
    }

    // ---- quarter-granular zero protocol (R7 form, proven) ----
    __shared__ int zmask;
    if (threadIdx.x == 0) zmask = 0;
    __syncthreads();                                // all grid reads retired
    if (threadIdx.x == 0) {
        __threadfence();
        int m = 0;
        int q0 = (p0 << 2) + q;
        int q1 = ((p0 + 1) << 2) + q;
        int tgt0 = 1 + (q > 0 ? 1 : 0) + (i0 > 0 ? 1 : 0);
        int tgt1 = 1 + (q > 0 ? 1 : 0);
        if (atomicAdd(&g_done[q0], 1) + 1 == tgt0) m |= 1;
        if (atomicAdd(&g_done[q1], 1) + 1 == tgt1) m |= 2;
        if (q < 3) {
            int j0 = (p0 << 2) + q + 1;
            int j1 = ((p0 + 1) << 2) + q + 1;
            if (atomicAdd(&g_done[j0], 1) + 1 == 2 + (i0 > 0 ? 1 : 0)) m |= 4;
            if (atomicAdd(&g_done[j1], 1) + 1 == 2) m |= 8;
        }
        if (has_ext) {
            int e0 = ((p0 + 2) << 2) + q;
            if (atomicAdd(&g_done[e0], 1) + 1 == 2 + (q > 0 ? 1 : 0)) m |= 16;
        }
        zmask = m;
    }
    __syncthreads();
    int m = zmask;
    if (m & 1)  zero_quarter((p0 << 2) + q,           threadIdx.x, pol);
    if (m & 2)  zero_quarter(((p0 + 1) << 2) + q,     threadIdx.x, pol);
    if (m & 4)  zero_quarter((p0 << 2) + q + 1,       threadIdx.x, pol);
    if (m & 8)  zero_quarter(((p0 + 1) << 2) + q + 1, threadIdx.x, pol);
    if (m & 16) zero_quarter(((p0 + 2) << 2) + q,     threadIdx.x, pol);
}

// ---------------------------------------------------------------------------
extern "C" void kernel_launch(void* const* d_in, const int* in_sizes, int n_in,
                              void* d_out, int out_size) {
    const int*   indices = (const int*)d_in[0];    // (B, M, 3) int32
    const float* values  = (const float*)d_in[1];  // (B, M) float32
    float* out = (float*)d_out;                    // (2, B) float32

    {
        int nthreads = BATCH * TPB_SCAT;            // 500,000
        int threads = 256;
        int blocks = (nthreads + threads - 1) / threads;
        scatter_kernel<<<blocks, threads>>>((const int4*)indices,
                                            (const float4*)values, out);
    }
    {
        reduce_zero_kernel<<<2048, 256>>>(out);
    }
}